// round 4
// baseline (speedup 1.0000x reference)
#include <cuda_runtime.h>
#include <cuda_fp16.h>
#include <math.h>
#include <stdint.h>

#define BS     16
#define SLEN   2048
#define DIM    1024
#define M_TOT  (BS * SLEN)   // 32768
#define NSPLIT 8

// Quantization scales (exact in fp32; SRA*SB == SA*SRB == 16516096)
#define Q_SA   15.875f       // 127/8        : states -> int8
#define Q_SRA  32512.0f      // 127/(8*2^-11): fp16 residual of states -> int8
#define Q_SB   508.0f        // 127/0.25     : WkT -> int8
#define Q_SRB  1040384.0f    // 127/(0.25*2^-11): fp16 residual of WkT -> int8
#define Q_INV  (1.0f / 16516096.0f)

// ---------------------------------------------------------------------------
// Scratch (__device__ globals; allocation-free rule)
// ---------------------------------------------------------------------------
__device__ __align__(16) __half  g_st_h[(size_t)M_TOT * DIM];   // 64MB
__device__ __align__(16) int8_t  g_st_r[(size_t)M_TOT * DIM];   // 32MB
__device__ __align__(16) int8_t  g_st_q[(size_t)M_TOT * DIM];   // 32MB
__device__ __align__(16) __half  g_wkT_h[(size_t)DIM * DIM];    // 2MB  WkT[n][k]
__device__ __align__(16) int8_t  g_wkT_q[(size_t)DIM * DIM];    // 1MB
__device__ __align__(16) int8_t  g_wkT_r[(size_t)DIM * DIM];    // 1MB
__device__ float g_ek_part[NSPLIT * M_TOT];
__device__ float g_eq_part[BS * 4];
__device__ __align__(16) float g_attn_part[32 * BS * DIM];

__device__ __forceinline__ uint32_t smem_u32(const void* p) {
    uint32_t a;
    asm("{ .reg .u64 t; cvta.to.shared.u64 t, %1; cvt.u32.u64 %0, t; }"
        : "=r"(a) : "l"(p));
    return a;
}

#define LDMX4(r0, r1, r2, r3, addr)                                          \
    asm volatile("ldmatrix.sync.aligned.m8n8.x4.shared.b16 {%0,%1,%2,%3}, [%4];" \
        : "=r"(r0), "=r"(r1), "=r"(r2), "=r"(r3) : "r"(addr))

#define MMAF16(c, a, b0, b1)                                                 \
    asm volatile("mma.sync.aligned.m16n8k16.row.col.f32.f16.f16.f32 "        \
        "{%0,%1,%2,%3}, {%4,%5,%6,%7}, {%8,%9}, {%0,%1,%2,%3};"              \
        : "+f"((c)[0]), "+f"((c)[1]), "+f"((c)[2]), "+f"((c)[3])             \
        : "r"((a)[0]), "r"((a)[1]), "r"((a)[2]), "r"((a)[3]),                \
          "r"(b0), "r"(b1))

#define MMAS8(c, a, b0, b1)                                                  \
    asm volatile("mma.sync.aligned.m16n8k32.row.col.s32.s8.s8.s32 "          \
        "{%0,%1,%2,%3}, {%4,%5,%6,%7}, {%8,%9}, {%0,%1,%2,%3};"              \
        : "+r"((c)[0]), "+r"((c)[1]), "+r"((c)[2]), "+r"((c)[3])             \
        : "r"((a)[0]), "r"((a)[1]), "r"((a)[2]), "r"((a)[3]),                \
          "r"(b0), "r"(b1))

#define CPASYNC16(dst, src)                                                  \
    asm volatile("cp.async.cg.shared.global [%0], [%1], 16;"                 \
                 :: "r"(dst), "l"(src))
#define CP_COMMIT()  asm volatile("cp.async.commit_group;" ::: "memory")
#define CP_WAIT0()   asm volatile("cp.async.wait_group 0;" ::: "memory")

__device__ __forceinline__ int clamp127(float x) {
    int v = __float2int_rn(x);
    return max(-127, min(127, v));
}
__device__ __forceinline__ uint32_t pack4(int a, int b, int c, int d) {
    return (uint32_t)(a & 0xFF) | ((uint32_t)(b & 0xFF) << 8) |
           ((uint32_t)(c & 0xFF) << 16) | ((uint32_t)(d & 0xFF) << 24);
}

// ---------------------------------------------------------------------------
// states -> fp16 hi + int8 residual + int8 primary
// ---------------------------------------------------------------------------
__global__ void __launch_bounds__(256) k_convert_states(const float* __restrict__ x) {
    const size_t i = ((size_t)blockIdx.x * 256 + threadIdx.x) * 4;
    const float4 v = *(const float4*)(x + i);
    const __half h0 = __float2half_rn(v.x), h1 = __float2half_rn(v.y);
    const __half h2 = __float2half_rn(v.z), h3 = __float2half_rn(v.w);
    __half2 p01, p23;
    p01.x = h0; p01.y = h1; p23.x = h2; p23.y = h3;
    uint2 hp;
    hp.x = *(const uint32_t*)&p01; hp.y = *(const uint32_t*)&p23;
    *(uint2*)(g_st_h + i) = hp;
    const int r0 = clamp127((v.x - __half2float(h0)) * Q_SRA);
    const int r1 = clamp127((v.y - __half2float(h1)) * Q_SRA);
    const int r2 = clamp127((v.z - __half2float(h2)) * Q_SRA);
    const int r3 = clamp127((v.w - __half2float(h3)) * Q_SRA);
    *(uint32_t*)(g_st_r + i) = pack4(r0, r1, r2, r3);
    const int q0 = clamp127(v.x * Q_SA), q1 = clamp127(v.y * Q_SA);
    const int q2 = clamp127(v.z * Q_SA), q3 = clamp127(v.w * Q_SA);
    *(uint32_t*)(g_st_q + i) = pack4(q0, q1, q2, q3);
}

// ---------------------------------------------------------------------------
// WkT (transpose) + fp16/int8/int8-res split.  WkT[d][v] = Wk[v][d]
// ---------------------------------------------------------------------------
__global__ void __launch_bounds__(256) k_convert_wkT(const float* __restrict__ Wk) {
    __shared__ float tile[32][33];
    const int tx = threadIdx.x, ty = threadIdx.y;        // (32, 8)
    const int v0 = blockIdx.y * 32, d0 = blockIdx.x * 32;
    #pragma unroll
    for (int j = 0; j < 4; j++)
        tile[ty + j * 8][tx] = Wk[(size_t)(v0 + ty + j * 8) * DIM + d0 + tx];
    __syncthreads();
    #pragma unroll
    for (int j = 0; j < 4; j++) {
        const int dy = ty + j * 8;
        const float val = tile[tx][dy];
        const __half h = __float2half_rn(val);
        const size_t o = (size_t)(d0 + dy) * DIM + v0 + tx;
        g_wkT_h[o] = h;
        g_wkT_q[o] = (int8_t)clamp127(val * Q_SB);
        g_wkT_r[o] = (int8_t)clamp127((val - __half2float(h)) * Q_SRB);
    }
}

// ---------------------------------------------------------------------------
// eq partials
// ---------------------------------------------------------------------------
__global__ void __launch_bounds__(256) k_qenergy(
        const float* __restrict__ query, const float* __restrict__ Wq,
        const float* __restrict__ bq,    const float* __restrict__ We) {
    const int b = blockIdx.x, q = blockIdx.y;
    const int tid = threadIdx.x;
    const int col = q * 256 + tid;
    __shared__ float qs[DIM];
    for (int v = tid; v < DIM; v += 256) qs[v] = query[b * DIM + v];
    __syncthreads();
    float acc = 0.f;
    #pragma unroll 4
    for (int v = 0; v < DIM; v++)
        acc = fmaf(qs[v], Wq[(size_t)v * DIM + col], acc);
    const float val = fmaxf(acc + bq[col], 0.f);
    float e = tanhf(val) * We[col];
    __shared__ float red[256];
    red[tid] = e; __syncthreads();
    for (int s = 128; s > 0; s >>= 1) {
        if (tid < s) red[tid] += red[tid + s];
        __syncthreads();
    }
    if (tid == 0) g_eq_part[b * 4 + q] = red[0];
}

// ---------------------------------------------------------------------------
// GEMM: fp16 primary + shared-scale int8 corrections, fused tanh*We epilogue.
// CTA 128(M) x 128(N), K in 32 slabs of 32, cp.async double-buffered.
// ---------------------------------------------------------------------------
#define OFF_AH   0          // 128 rows * 80B  (64B fp16 data)
#define OFF_BH   10240      // 128 rows * 80B
#define OFF_AR   20480      // 128 rows * 48B  (32B int8 data)
#define OFF_AQ   26624
#define OFF_BQ   32768
#define OFF_BR   38912
#define BUF_SZ   45056
#define RED_OFF  (2 * BUF_SZ)                 // 90112
#define GEMM_SMEM (RED_OFF + 4 * 128 * 4)     // 92160

__device__ __forceinline__ void issue_slab(
        uint32_t sb,
        const __half* __restrict__ Ah, const int8_t* __restrict__ Ar,
        const int8_t* __restrict__ Aq,
        const __half* __restrict__ Bh, const int8_t* __restrict__ Bq,
        const int8_t* __restrict__ Br, int k0, int tid) {
    {
        const int row = tid >> 2, seg = tid & 3;
        CPASYNC16(sb + OFF_AH + row * 80 + seg * 16,
                  Ah + (size_t)row * DIM + k0 + seg * 8);
        CPASYNC16(sb + OFF_BH + row * 80 + seg * 16,
                  Bh + (size_t)row * DIM + k0 + seg * 8);
    }
    {
        const int row = (tid & 255) >> 1, seg = tid & 1;
        if (tid < 256) {
            CPASYNC16(sb + OFF_AR + row * 48 + seg * 16,
                      Ar + (size_t)row * DIM + k0 + seg * 16);
            CPASYNC16(sb + OFF_BQ + row * 48 + seg * 16,
                      Bq + (size_t)row * DIM + k0 + seg * 16);
        } else {
            CPASYNC16(sb + OFF_AQ + row * 48 + seg * 16,
                      Aq + (size_t)row * DIM + k0 + seg * 16);
            CPASYNC16(sb + OFF_BR + row * 48 + seg * 16,
                      Br + (size_t)row * DIM + k0 + seg * 16);
        }
    }
}

__global__ void __launch_bounds__(512, 1) k_gemm_mma(
        const float* __restrict__ bk, const float* __restrict__ We_k) {
    extern __shared__ char smem[];
    const uint32_t sbase = smem_u32(smem);
    const int tid = threadIdx.x;
    const int wid = tid >> 5;
    const int lid = tid & 31;
    const int n_blk = blockIdx.x;   // 0..7
    const int m_blk = blockIdx.y;   // 0..255

    const int wm = wid & 3, wn = wid >> 2;
    const int m0 = wm * 32, n0 = wn * 32;

    // ldmatrix lane addressing (same fragment patterns for f16 and s8)
    const int a_r  = (lid & 7) + ((lid >> 3) & 1) * 8;
    const int a_cs = (lid >> 4) * 16;
    const int b_r  = (lid & 7) + (lid >> 4) * 8;
    const int b_ks = ((lid >> 3) & 1) * 16;

    const __half* Ah = g_st_h + (size_t)m_blk * 128 * DIM;
    const int8_t* Ar = g_st_r + (size_t)m_blk * 128 * DIM;
    const int8_t* Aq = g_st_q + (size_t)m_blk * 128 * DIM;
    const __half* Bh = g_wkT_h + (size_t)n_blk * 128 * DIM;
    const int8_t* Bq = g_wkT_q + (size_t)n_blk * 128 * DIM;
    const int8_t* Br = g_wkT_r + (size_t)n_blk * 128 * DIM;

    float accf[2][4][4];
    int   acci[2][4][4];
    #pragma unroll
    for (int i = 0; i < 2; i++)
        #pragma unroll
        for (int j = 0; j < 4; j++)
            #pragma unroll
            for (int c = 0; c < 4; c++) { accf[i][j][c] = 0.f; acci[i][j][c] = 0; }

    issue_slab(sbase, Ah, Ar, Aq, Bh, Bq, Br, 0, tid);
    CP_COMMIT();

    for (int s = 0; s < 32; s++) {
        CP_WAIT0();
        __syncthreads();
        if (s < 31) {
            issue_slab(sbase + (uint32_t)((s + 1) & 1) * BUF_SZ,
                       Ah, Ar, Aq, Bh, Bq, Br, (s + 1) * 32, tid);
            CP_COMMIT();
        }
        const uint32_t ab = sbase + (uint32_t)(s & 1) * BUF_SZ;

        // ---- int8 correction passes (whole K=32 slab per mma) ----
        {
            uint32_t a8[2][4], b8[4][2];
            #pragma unroll
            for (int fm = 0; fm < 2; fm++)
                LDMX4(a8[fm][0], a8[fm][1], a8[fm][2], a8[fm][3],
                      ab + OFF_AR + (uint32_t)((m0 + fm * 16 + a_r) * 48 + a_cs));
            #pragma unroll
            for (int q = 0; q < 2; q++)
                LDMX4(b8[2 * q][0], b8[2 * q][1], b8[2 * q + 1][0], b8[2 * q + 1][1],
                      ab + OFF_BQ + (uint32_t)((n0 + q * 16 + b_r) * 48 + b_ks));
            #pragma unroll
            for (int fm = 0; fm < 2; fm++)
                #pragma unroll
                for (int fn = 0; fn < 4; fn++)
                    MMAS8(acci[fm][fn], a8[fm], b8[fn][0], b8[fn][1]);

            #pragma unroll
            for (int fm = 0; fm < 2; fm++)
                LDMX4(a8[fm][0], a8[fm][1], a8[fm][2], a8[fm][3],
                      ab + OFF_AQ + (uint32_t)((m0 + fm * 16 + a_r) * 48 + a_cs));
            #pragma unroll
            for (int q = 0; q < 2; q++)
                LDMX4(b8[2 * q][0], b8[2 * q][1], b8[2 * q + 1][0], b8[2 * q + 1][1],
                      ab + OFF_BR + (uint32_t)((n0 + q * 16 + b_r) * 48 + b_ks));
            #pragma unroll
            for (int fm = 0; fm < 2; fm++)
                #pragma unroll
                for (int fn = 0; fn < 4; fn++)
                    MMAS8(acci[fm][fn], a8[fm], b8[fn][0], b8[fn][1]);
        }

        // ---- fp16 primary pass (two K=16 steps) ----
        #pragma unroll
        for (int kk = 0; kk < 2; kk++) {
            const int kb = kk * 32;
            uint32_t ah[2][4], bh[4][2];
            #pragma unroll
            for (int fm = 0; fm < 2; fm++)
                LDMX4(ah[fm][0], ah[fm][1], ah[fm][2], ah[fm][3],
                      ab + OFF_AH + (uint32_t)((m0 + fm * 16 + a_r) * 80 + kb + a_cs));
            #pragma unroll
            for (int q = 0; q < 2; q++)
                LDMX4(bh[2 * q][0], bh[2 * q][1], bh[2 * q + 1][0], bh[2 * q + 1][1],
                      ab + OFF_BH + (uint32_t)((n0 + q * 16 + b_r) * 80 + kb + b_ks));
            #pragma unroll
            for (int fm = 0; fm < 2; fm++)
                #pragma unroll
                for (int fn = 0; fn < 4; fn++)
                    MMAF16(accf[fm][fn], ah[fm], bh[fn][0], bh[fn][1]);
        }
    }

    // Fused epilogue: tanh(relu(k + bk)) * We reduced over this 128-N tile
    float bkv[4][2], wev[4][2];
    #pragma unroll
    for (int fn = 0; fn < 4; fn++)
        #pragma unroll
        for (int j = 0; j < 2; j++) {
            const int n = n_blk * 128 + n0 + fn * 8 + (lid & 3) * 2 + j;
            bkv[fn][j] = bk[n];
            wev[fn][j] = We_k[n];
        }

    float* sred = (float*)(smem + RED_OFF);
    #pragma unroll
    for (int fm = 0; fm < 2; fm++)
        #pragma unroll
        for (int ch = 0; ch < 2; ch++) {
            float p = 0.f;
            #pragma unroll
            for (int fn = 0; fn < 4; fn++)
                #pragma unroll
                for (int j = 0; j < 2; j++) {
                    float v = accf[fm][fn][ch * 2 + j] +
                              (float)acci[fm][fn][ch * 2 + j] * Q_INV + bkv[fn][j];
                    v = fmaxf(v, 0.f);
                    p = fmaf(tanhf(v), wev[fn][j], p);
                }
            p += __shfl_down_sync(0xffffffffu, p, 1, 4);
            p += __shfl_down_sync(0xffffffffu, p, 2, 4);
            if ((lid & 3) == 0)
                sred[wn * 128 + m0 + fm * 16 + ch * 8 + (lid >> 2)] = p;
        }
    __syncthreads();
    if (tid < 128) {
        const float e = sred[tid] + sred[128 + tid] + sred[256 + tid] + sred[384 + tid];
        g_ek_part[n_blk * M_TOT + m_blk * 128 + tid] = e;
    }
}

// ---------------------------------------------------------------------------
// softmax over s
// ---------------------------------------------------------------------------
__global__ void __launch_bounds__(256) k_softmax(
        const float* __restrict__ be, float* __restrict__ out_w) {
    const int b = blockIdx.x;
    const int tid = threadIdx.x;
    const float base = g_eq_part[b * 4 + 0] + g_eq_part[b * 4 + 1] +
                       g_eq_part[b * 4 + 2] + g_eq_part[b * 4 + 3] + be[0];
    float e[8];
    float lmax = -1e30f;
    #pragma unroll
    for (int r = 0; r < 8; r++) {
        const int s = r * 256 + tid;
        float v = base;
        #pragma unroll
        for (int p = 0; p < NSPLIT; p++)
            v += g_ek_part[p * M_TOT + b * SLEN + s];
        e[r] = v;
        lmax = fmaxf(lmax, v);
    }
    __shared__ float red[256];
    red[tid] = lmax; __syncthreads();
    for (int s = 128; s > 0; s >>= 1) {
        if (tid < s) red[tid] = fmaxf(red[tid], red[tid + s]);
        __syncthreads();
    }
    const float gmax = red[0];
    __syncthreads();
    float lsum = 0.f;
    #pragma unroll
    for (int r = 0; r < 8; r++) {
        e[r] = expf(e[r] - gmax);
        lsum += e[r];
    }
    red[tid] = lsum; __syncthreads();
    for (int s = 128; s > 0; s >>= 1) {
        if (tid < s) red[tid] += red[tid + s];
        __syncthreads();
    }
    const float inv = 1.f / red[0];
    #pragma unroll
    for (int r = 0; r < 8; r++)
        out_w[b * SLEN + r * 256 + tid] = e[r] * inv;
}

// ---------------------------------------------------------------------------
// attn partials + reduce
// ---------------------------------------------------------------------------
__global__ void __launch_bounds__(256) k_attn_part(
        const float* __restrict__ states, const float* __restrict__ w) {
    const int sc = blockIdx.x;   // 0..31
    const int b  = blockIdx.y;   // 0..15
    const int tid = threadIdx.x;
    const float4* st4 = (const float4*)states;
    float4 acc = make_float4(0.f, 0.f, 0.f, 0.f);
    const int s0 = sc * 64;
    #pragma unroll 4
    for (int sl = 0; sl < 64; sl++) {
        const int s = s0 + sl;
        const float wv = w[b * SLEN + s];
        const float4 v = st4[(size_t)(b * SLEN + s) * 256 + tid];
        acc.x = fmaf(wv, v.x, acc.x);
        acc.y = fmaf(wv, v.y, acc.y);
        acc.z = fmaf(wv, v.z, acc.z);
        acc.w = fmaf(wv, v.w, acc.w);
    }
    *(float4*)(g_attn_part + (size_t)(sc * BS + b) * DIM + tid * 4) = acc;
}

__global__ void __launch_bounds__(256) k_attn_reduce(float* __restrict__ out_attn) {
    const int idx = blockIdx.x * 256 + threadIdx.x;
    const int b = idx >> 10;
    const int d = idx & 1023;
    float s = 0.f;
    #pragma unroll
    for (int p = 0; p < 32; p++)
        s += g_attn_part[(size_t)(p * BS + b) * DIM + d];
    out_attn[idx] = s;
}

// ---------------------------------------------------------------------------
extern "C" void kernel_launch(void* const* d_in, const int* in_sizes, int n_in,
                              void* d_out, int out_size) {
    const float* query  = (const float*)d_in[0];
    const float* states = (const float*)d_in[1];
    const float* Wq     = (const float*)d_in[2];
    const float* bq     = (const float*)d_in[3];
    const float* Wk     = (const float*)d_in[4];
    const float* bk     = (const float*)d_in[5];
    const float* We     = (const float*)d_in[6];
    const float* be     = (const float*)d_in[7];

    float* out      = (float*)d_out;
    float* out_w    = out;                 // attn_weights (16, 2048)
    float* out_attn = out + BS * SLEN;     // attn         (16, 1024)

    cudaFuncSetAttribute(k_gemm_mma, cudaFuncAttributeMaxDynamicSharedMemorySize,
                         GEMM_SMEM);

    k_convert_states<<<M_TOT * DIM / 4 / 256, 256>>>(states);
    k_convert_wkT<<<dim3(32, 32), dim3(32, 8)>>>(Wk);
    k_qenergy<<<dim3(BS, 4), 256>>>(query, Wq, bq, We);
    k_gemm_mma<<<dim3(NSPLIT, M_TOT / 128), 512, GEMM_SMEM>>>(bk, We + DIM);
    k_softmax<<<BS, 256>>>(be, out_w);
    k_attn_part<<<dim3(32, BS), 256>>>(states, out_w);
    k_attn_reduce<<<BS * DIM / 256, 256>>>(out_attn);
}

// round 5
// speedup vs baseline: 2.5523x; 2.5523x over previous
#include <cuda_runtime.h>
#include <cuda_fp16.h>
#include <math.h>
#include <stdint.h>

#define BS     16
#define SLEN   2048
#define DIM    1024
#define M_TOT  (BS * SLEN)   // 32768
#define NSPLIT 8

// ---------------------------------------------------------------------------
// Scratch (__device__ globals; allocation-free rule)
// ---------------------------------------------------------------------------
__device__ __align__(16) __half g_st_h[(size_t)M_TOT * DIM];    // 64MB
__device__ __align__(16) __half g_wkT_h[(size_t)DIM * DIM];     // 2MB WkT[n][k]
__device__ __align__(16) __half g_wkT_l[(size_t)DIM * DIM];     // 2MB residual*2048
__device__ float g_ek_part[NSPLIT * M_TOT];
__device__ float g_eq_part[BS * 4];
__device__ __align__(16) float g_attn_part[32 * BS * DIM];

__device__ __forceinline__ uint32_t smem_u32(const void* p) {
    uint32_t a;
    asm("{ .reg .u64 t; cvta.to.shared.u64 t, %1; cvt.u32.u64 %0, t; }"
        : "=r"(a) : "l"(p));
    return a;
}

#define LDMX4(r0, r1, r2, r3, addr)                                          \
    asm volatile("ldmatrix.sync.aligned.m8n8.x4.shared.b16 {%0,%1,%2,%3}, [%4];" \
        : "=r"(r0), "=r"(r1), "=r"(r2), "=r"(r3) : "r"(addr))

#define MMAF16(c, a, b0, b1)                                                 \
    asm volatile("mma.sync.aligned.m16n8k16.row.col.f32.f16.f16.f32 "        \
        "{%0,%1,%2,%3}, {%4,%5,%6,%7}, {%8,%9}, {%0,%1,%2,%3};"              \
        : "+f"((c)[0]), "+f"((c)[1]), "+f"((c)[2]), "+f"((c)[3])             \
        : "r"((a)[0]), "r"((a)[1]), "r"((a)[2]), "r"((a)[3]),                \
          "r"(b0), "r"(b1))

#define CPASYNC16(dst, src)                                                  \
    asm volatile("cp.async.cg.shared.global [%0], [%1], 16;"                 \
                 :: "r"(dst), "l"(src))
#define CP_COMMIT()  asm volatile("cp.async.commit_group;" ::: "memory")
#define CP_WAIT0()   asm volatile("cp.async.wait_group 0;" ::: "memory")

// ---------------------------------------------------------------------------
// states -> fp16
// ---------------------------------------------------------------------------
__global__ void __launch_bounds__(256) k_convert_states(const float* __restrict__ x) {
    const size_t i = ((size_t)blockIdx.x * 256 + threadIdx.x) * 4;
    const float4 v = *(const float4*)(x + i);
    __half2 p01, p23;
    p01.x = __float2half_rn(v.x); p01.y = __float2half_rn(v.y);
    p23.x = __float2half_rn(v.z); p23.y = __float2half_rn(v.w);
    uint2 hp;
    hp.x = *(const uint32_t*)&p01; hp.y = *(const uint32_t*)&p23;
    *(uint2*)(g_st_h + i) = hp;
}

// ---------------------------------------------------------------------------
// WkT (transpose) + fp16 hi/lo split (lo scaled 2048).  WkT[d][v] = Wk[v][d]
// ---------------------------------------------------------------------------
__global__ void __launch_bounds__(256) k_convert_wkT(const float* __restrict__ Wk) {
    __shared__ float tile[32][33];
    const int tx = threadIdx.x, ty = threadIdx.y;        // (32, 8)
    const int v0 = blockIdx.y * 32, d0 = blockIdx.x * 32;
    #pragma unroll
    for (int j = 0; j < 4; j++)
        tile[ty + j * 8][tx] = Wk[(size_t)(v0 + ty + j * 8) * DIM + d0 + tx];
    __syncthreads();
    #pragma unroll
    for (int j = 0; j < 4; j++) {
        const int dy = ty + j * 8;
        const float val = tile[tx][dy];
        const __half h = __float2half_rn(val);
        const size_t o = (size_t)(d0 + dy) * DIM + v0 + tx;
        g_wkT_h[o] = h;
        g_wkT_l[o] = __float2half_rn((val - __half2float(h)) * 2048.0f);
    }
}

// ---------------------------------------------------------------------------
// eq partials
// ---------------------------------------------------------------------------
__global__ void __launch_bounds__(256) k_qenergy(
        const float* __restrict__ query, const float* __restrict__ Wq,
        const float* __restrict__ bq,    const float* __restrict__ We) {
    const int b = blockIdx.x, q = blockIdx.y;
    const int tid = threadIdx.x;
    const int col = q * 256 + tid;
    __shared__ float qs[DIM];
    for (int v = tid; v < DIM; v += 256) qs[v] = query[b * DIM + v];
    __syncthreads();
    float acc = 0.f;
    #pragma unroll 4
    for (int v = 0; v < DIM; v++)
        acc = fmaf(qs[v], Wq[(size_t)v * DIM + col], acc);
    const float val = fmaxf(acc + bq[col], 0.f);
    float e = tanhf(val) * We[col];
    __shared__ float red[256];
    red[tid] = e; __syncthreads();
    for (int s = 128; s > 0; s >>= 1) {
        if (tid < s) red[tid] += red[tid + s];
        __syncthreads();
    }
    if (tid == 0) g_eq_part[b * 4 + q] = red[0];
}

// ---------------------------------------------------------------------------
// GEMM: 2-pass fp16 (A single, B hi + B lo*2048), fused tanh*We epilogue.
// CTA 128(M) x 128(N), K in 16 slabs of 64, cp.async double-buffered.
// smem row pitch 144B (128B payload): conflict-free ldmatrix.
// ---------------------------------------------------------------------------
#define PITCH    144
#define TILE_B   (128 * PITCH)         // 18432
#define OFF_A    0
#define OFF_BH   TILE_B
#define OFF_BL   (2 * TILE_B)
#define BUF_SZ   (3 * TILE_B)          // 55296
#define RED_OFF  (2 * BUF_SZ)          // 110592
#define GEMM_SMEM (RED_OFF + 4 * 128 * 4)   // 112640

__device__ __forceinline__ void issue_slab(
        uint32_t sb,
        const __half* __restrict__ A, const __half* __restrict__ Bh,
        const __half* __restrict__ Bl, int k0, int tid) {
    #pragma unroll
    for (int p = 0; p < 2; p++) {
        const int idx = p * 512 + tid;      // 1024 chunks of 16B per tile
        const int row = idx >> 3, seg = idx & 7;
        const uint32_t d = (uint32_t)(row * PITCH + seg * 16);
        const size_t g = (size_t)row * DIM + k0 + seg * 8;
        CPASYNC16(sb + OFF_A + d, A + g);
        CPASYNC16(sb + OFF_BH + d, Bh + g);
        CPASYNC16(sb + OFF_BL + d, Bl + g);
    }
}

__global__ void __launch_bounds__(512, 1) k_gemm_mma(
        const float* __restrict__ bk, const float* __restrict__ We_k) {
    extern __shared__ char smem[];
    const uint32_t sbase = smem_u32(smem);
    const int tid = threadIdx.x;
    const int wid = tid >> 5;
    const int lid = tid & 31;
    const int n_blk = blockIdx.x;   // 0..7
    const int m_blk = blockIdx.y;   // 0..255

    const int wm = wid & 3, wn = wid >> 2;
    const int m0 = wm * 32, n0 = wn * 32;

    // ldmatrix lane addressing
    const int a_r  = (lid & 7) + ((lid >> 3) & 1) * 8;
    const int a_cs = (lid >> 4) * 16;
    const int b_r  = (lid & 7) + (lid >> 4) * 8;
    const int b_ks = ((lid >> 3) & 1) * 16;

    const __half* A  = g_st_h + (size_t)m_blk * 128 * DIM;
    const __half* Bh = g_wkT_h + (size_t)n_blk * 128 * DIM;
    const __half* Bl = g_wkT_l + (size_t)n_blk * 128 * DIM;

    float acch[2][4][4], accl[2][4][4];
    #pragma unroll
    for (int i = 0; i < 2; i++)
        #pragma unroll
        for (int j = 0; j < 4; j++)
            #pragma unroll
            for (int c = 0; c < 4; c++) { acch[i][j][c] = 0.f; accl[i][j][c] = 0.f; }

    issue_slab(sbase, A, Bh, Bl, 0, tid);
    CP_COMMIT();

    for (int s = 0; s < 16; s++) {
        CP_WAIT0();
        __syncthreads();
        if (s < 15) {
            issue_slab(sbase + (uint32_t)((s + 1) & 1) * BUF_SZ, A, Bh, Bl,
                       (s + 1) * 64, tid);
            CP_COMMIT();
        }
        const uint32_t ab = sbase + (uint32_t)(s & 1) * BUF_SZ;

        #pragma unroll
        for (int kk = 0; kk < 4; kk++) {
            const int kb = kk * 32;    // 16 fp16 per k-step
            uint32_t ah[2][4], bf[4][2];
            #pragma unroll
            for (int fm = 0; fm < 2; fm++)
                LDMX4(ah[fm][0], ah[fm][1], ah[fm][2], ah[fm][3],
                      ab + OFF_A + (uint32_t)((m0 + fm * 16 + a_r) * PITCH + kb + a_cs));
            // hi pass
            #pragma unroll
            for (int q = 0; q < 2; q++)
                LDMX4(bf[2 * q][0], bf[2 * q][1], bf[2 * q + 1][0], bf[2 * q + 1][1],
                      ab + OFF_BH + (uint32_t)((n0 + q * 16 + b_r) * PITCH + kb + b_ks));
            #pragma unroll
            for (int fm = 0; fm < 2; fm++)
                #pragma unroll
                for (int fn = 0; fn < 4; fn++)
                    MMAF16(acch[fm][fn], ah[fm], bf[fn][0], bf[fn][1]);
            // lo pass
            #pragma unroll
            for (int q = 0; q < 2; q++)
                LDMX4(bf[2 * q][0], bf[2 * q][1], bf[2 * q + 1][0], bf[2 * q + 1][1],
                      ab + OFF_BL + (uint32_t)((n0 + q * 16 + b_r) * PITCH + kb + b_ks));
            #pragma unroll
            for (int fm = 0; fm < 2; fm++)
                #pragma unroll
                for (int fn = 0; fn < 4; fn++)
                    MMAF16(accl[fm][fn], ah[fm], bf[fn][0], bf[fn][1]);
        }
    }

    // Fused epilogue: tanh(relu(k + bk)) * We reduced over this 128-N tile
    float bkv[4][2], wev[4][2];
    #pragma unroll
    for (int fn = 0; fn < 4; fn++)
        #pragma unroll
        for (int j = 0; j < 2; j++) {
            const int n = n_blk * 128 + n0 + fn * 8 + (lid & 3) * 2 + j;
            bkv[fn][j] = bk[n];
            wev[fn][j] = We_k[n];
        }

    float* sred = (float*)(smem + RED_OFF);
    #pragma unroll
    for (int fm = 0; fm < 2; fm++)
        #pragma unroll
        for (int ch = 0; ch < 2; ch++) {
            float p = 0.f;
            #pragma unroll
            for (int fn = 0; fn < 4; fn++)
                #pragma unroll
                for (int j = 0; j < 2; j++) {
                    float v = acch[fm][fn][ch * 2 + j] +
                              accl[fm][fn][ch * 2 + j] * (1.0f / 2048.0f) +
                              bkv[fn][j];
                    v = fmaxf(v, 0.f);
                    p = fmaf(tanhf(v), wev[fn][j], p);
                }
            p += __shfl_down_sync(0xffffffffu, p, 1, 4);
            p += __shfl_down_sync(0xffffffffu, p, 2, 4);
            if ((lid & 3) == 0)
                sred[wn * 128 + m0 + fm * 16 + ch * 8 + (lid >> 2)] = p;
        }
    __syncthreads();
    if (tid < 128) {
        const float e = sred[tid] + sred[128 + tid] + sred[256 + tid] + sred[384 + tid];
        g_ek_part[n_blk * M_TOT + m_blk * 128 + tid] = e;
    }
}

// ---------------------------------------------------------------------------
// softmax over s
// ---------------------------------------------------------------------------
__global__ void __launch_bounds__(256) k_softmax(
        const float* __restrict__ be, float* __restrict__ out_w) {
    const int b = blockIdx.x;
    const int tid = threadIdx.x;
    const float base = g_eq_part[b * 4 + 0] + g_eq_part[b * 4 + 1] +
                       g_eq_part[b * 4 + 2] + g_eq_part[b * 4 + 3] + be[0];
    float e[8];
    float lmax = -1e30f;
    #pragma unroll
    for (int r = 0; r < 8; r++) {
        const int s = r * 256 + tid;
        float v = base;
        #pragma unroll
        for (int p = 0; p < NSPLIT; p++)
            v += g_ek_part[p * M_TOT + b * SLEN + s];
        e[r] = v;
        lmax = fmaxf(lmax, v);
    }
    __shared__ float red[256];
    red[tid] = lmax; __syncthreads();
    for (int s = 128; s > 0; s >>= 1) {
        if (tid < s) red[tid] = fmaxf(red[tid], red[tid + s]);
        __syncthreads();
    }
    const float gmax = red[0];
    __syncthreads();
    float lsum = 0.f;
    #pragma unroll
    for (int r = 0; r < 8; r++) {
        e[r] = expf(e[r] - gmax);
        lsum += e[r];
    }
    red[tid] = lsum; __syncthreads();
    for (int s = 128; s > 0; s >>= 1) {
        if (tid < s) red[tid] += red[tid + s];
        __syncthreads();
    }
    const float inv = 1.f / red[0];
    #pragma unroll
    for (int r = 0; r < 8; r++)
        out_w[b * SLEN + r * 256 + tid] = e[r] * inv;
}

// ---------------------------------------------------------------------------
// attn partials + reduce
// ---------------------------------------------------------------------------
__global__ void __launch_bounds__(256) k_attn_part(
        const float* __restrict__ states, const float* __restrict__ w) {
    const int sc = blockIdx.x;   // 0..31
    const int b  = blockIdx.y;   // 0..15
    const int tid = threadIdx.x;
    const float4* st4 = (const float4*)states;
    float4 acc = make_float4(0.f, 0.f, 0.f, 0.f);
    const int s0 = sc * 64;
    #pragma unroll 4
    for (int sl = 0; sl < 64; sl++) {
        const int s = s0 + sl;
        const float wv = w[b * SLEN + s];
        const float4 v = st4[(size_t)(b * SLEN + s) * 256 + tid];
        acc.x = fmaf(wv, v.x, acc.x);
        acc.y = fmaf(wv, v.y, acc.y);
        acc.z = fmaf(wv, v.z, acc.z);
        acc.w = fmaf(wv, v.w, acc.w);
    }
    *(float4*)(g_attn_part + (size_t)(sc * BS + b) * DIM + tid * 4) = acc;
}

__global__ void __launch_bounds__(256) k_attn_reduce(float* __restrict__ out_attn) {
    const int idx = blockIdx.x * 256 + threadIdx.x;
    const int b = idx >> 10;
    const int d = idx & 1023;
    float s = 0.f;
    #pragma unroll
    for (int p = 0; p < 32; p++)
        s += g_attn_part[(size_t)(p * BS + b) * DIM + d];
    out_attn[idx] = s;
}

// ---------------------------------------------------------------------------
extern "C" void kernel_launch(void* const* d_in, const int* in_sizes, int n_in,
                              void* d_out, int out_size) {
    const float* query  = (const float*)d_in[0];
    const float* states = (const float*)d_in[1];
    const float* Wq     = (const float*)d_in[2];
    const float* bq     = (const float*)d_in[3];
    const float* Wk     = (const float*)d_in[4];
    const float* bk     = (const float*)d_in[5];
    const float* We     = (const float*)d_in[6];
    const float* be     = (const float*)d_in[7];

    float* out      = (float*)d_out;
    float* out_w    = out;                 // attn_weights (16, 2048)
    float* out_attn = out + BS * SLEN;     // attn         (16, 1024)

    cudaFuncSetAttribute(k_gemm_mma, cudaFuncAttributeMaxDynamicSharedMemorySize,
                         GEMM_SMEM);

    k_convert_states<<<M_TOT * DIM / 4 / 256, 256>>>(states);
    k_convert_wkT<<<dim3(32, 32), dim3(32, 8)>>>(Wk);
    k_qenergy<<<dim3(BS, 4), 256>>>(query, Wq, bq, We);
    k_gemm_mma<<<dim3(NSPLIT, M_TOT / 128), 512, GEMM_SMEM>>>(bk, We + DIM);
    k_softmax<<<BS, 256>>>(be, out_w);
    k_attn_part<<<dim3(32, BS), 256>>>(states, out_w);
    k_attn_reduce<<<BS * DIM / 256, 256>>>(out_attn);
}

// round 6
// speedup vs baseline: 3.7619x; 1.4740x over previous
#include <cuda_runtime.h>
#include <cuda_fp16.h>
#include <math.h>
#include <stdint.h>

#define BS     16
#define SLEN   2048
#define DIM    1024
#define M_TOT  (BS * SLEN)   // 32768
#define NSPLIT 8

// ---------------------------------------------------------------------------
// Scratch (__device__ globals; allocation-free rule)
// ---------------------------------------------------------------------------
__device__ __align__(16) __half g_st_h[(size_t)M_TOT * DIM];    // 64MB
__device__ __align__(16) __half g_wkT_h[(size_t)DIM * DIM];     // 2MB WkT[n][k]
__device__ float g_ek_part[NSPLIT * M_TOT];
__device__ float g_eq_part[BS * 4];
__device__ __align__(16) float g_attn_part[32 * BS * DIM];

__device__ __forceinline__ uint32_t smem_u32(const void* p) {
    uint32_t a;
    asm("{ .reg .u64 t; cvta.to.shared.u64 t, %1; cvt.u32.u64 %0, t; }"
        : "=r"(a) : "l"(p));
    return a;
}

#define LDMX4(r0, r1, r2, r3, addr)                                          \
    asm volatile("ldmatrix.sync.aligned.m8n8.x4.shared.b16 {%0,%1,%2,%3}, [%4];" \
        : "=r"(r0), "=r"(r1), "=r"(r2), "=r"(r3) : "r"(addr))

#define MMAF16(c, a, b0, b1)                                                 \
    asm volatile("mma.sync.aligned.m16n8k16.row.col.f32.f16.f16.f32 "        \
        "{%0,%1,%2,%3}, {%4,%5,%6,%7}, {%8,%9}, {%0,%1,%2,%3};"              \
        : "+f"((c)[0]), "+f"((c)[1]), "+f"((c)[2]), "+f"((c)[3])             \
        : "r"((a)[0]), "r"((a)[1]), "r"((a)[2]), "r"((a)[3]),                \
          "r"(b0), "r"(b1))

#define CPASYNC16(dst, src)                                                  \
    asm volatile("cp.async.cg.shared.global [%0], [%1], 16;"                 \
                 :: "r"(dst), "l"(src))
#define CP_COMMIT()  asm volatile("cp.async.commit_group;" ::: "memory")
#define CP_WAIT0()   asm volatile("cp.async.wait_group 0;" ::: "memory")

// ---------------------------------------------------------------------------
// states -> fp16
// ---------------------------------------------------------------------------
__global__ void __launch_bounds__(256) k_convert_states(const float* __restrict__ x) {
    const size_t i = ((size_t)blockIdx.x * 256 + threadIdx.x) * 4;
    const float4 v = *(const float4*)(x + i);
    __half2 p01, p23;
    p01.x = __float2half_rn(v.x); p01.y = __float2half_rn(v.y);
    p23.x = __float2half_rn(v.z); p23.y = __float2half_rn(v.w);
    uint2 hp;
    hp.x = *(const uint32_t*)&p01; hp.y = *(const uint32_t*)&p23;
    *(uint2*)(g_st_h + i) = hp;
}

// ---------------------------------------------------------------------------
// WkT (transpose) + fp16.  WkT[d][v] = Wk[v][d]
// ---------------------------------------------------------------------------
__global__ void __launch_bounds__(256) k_convert_wkT(const float* __restrict__ Wk) {
    __shared__ float tile[32][33];
    const int tx = threadIdx.x, ty = threadIdx.y;        // (32, 8)
    const int v0 = blockIdx.y * 32, d0 = blockIdx.x * 32;
    #pragma unroll
    for (int j = 0; j < 4; j++)
        tile[ty + j * 8][tx] = Wk[(size_t)(v0 + ty + j * 8) * DIM + d0 + tx];
    __syncthreads();
    #pragma unroll
    for (int j = 0; j < 4; j++) {
        const int dy = ty + j * 8;
        g_wkT_h[(size_t)(d0 + dy) * DIM + v0 + tx] = __float2half_rn(tile[tx][dy]);
    }
}

// ---------------------------------------------------------------------------
// eq partials
// ---------------------------------------------------------------------------
__global__ void __launch_bounds__(256) k_qenergy(
        const float* __restrict__ query, const float* __restrict__ Wq,
        const float* __restrict__ bq,    const float* __restrict__ We) {
    const int b = blockIdx.x, q = blockIdx.y;
    const int tid = threadIdx.x;
    const int col = q * 256 + tid;
    __shared__ float qs[DIM];
    for (int v = tid; v < DIM; v += 256) qs[v] = query[b * DIM + v];
    __syncthreads();
    float acc = 0.f;
    #pragma unroll 4
    for (int v = 0; v < DIM; v++)
        acc = fmaf(qs[v], Wq[(size_t)v * DIM + col], acc);
    const float val = fmaxf(acc + bq[col], 0.f);
    float e = tanhf(val) * We[col];
    __shared__ float red[256];
    red[tid] = e; __syncthreads();
    for (int s = 128; s > 0; s >>= 1) {
        if (tid < s) red[tid] += red[tid + s];
        __syncthreads();
    }
    if (tid == 0) g_eq_part[b * 4 + q] = red[0];
}

// ---------------------------------------------------------------------------
// GEMM: single-pass fp16, fused tanh*We epilogue reduction.
// CTA 128(M) x 128(N), K in 16 slabs of 64, cp.async double-buffered.
// smem row pitch 144B: conflict-free ldmatrix. 2 CTAs/SM.
// ---------------------------------------------------------------------------
#define PITCH    144
#define TILE_B   (128 * PITCH)         // 18432
#define OFF_A    0
#define OFF_B    TILE_B
#define BUF_SZ   (2 * TILE_B)          // 36864
#define RED_OFF  (2 * BUF_SZ)          // 73728
#define GEMM_SMEM (RED_OFF + 4 * 128 * 4)   // 75776

__device__ __forceinline__ void issue_slab(
        uint32_t sb, const __half* __restrict__ A,
        const __half* __restrict__ B, int k0, int tid) {
    #pragma unroll
    for (int p = 0; p < 2; p++) {
        const int idx = p * 512 + tid;      // 1024 chunks of 16B per tile
        const int row = idx >> 3, seg = idx & 7;
        const uint32_t d = (uint32_t)(row * PITCH + seg * 16);
        const size_t g = (size_t)row * DIM + k0 + seg * 8;
        CPASYNC16(sb + OFF_A + d, A + g);
        CPASYNC16(sb + OFF_B + d, B + g);
    }
}

__global__ void __launch_bounds__(512, 2) k_gemm_mma(
        const float* __restrict__ bk, const float* __restrict__ We_k) {
    extern __shared__ char smem[];
    const uint32_t sbase = smem_u32(smem);
    const int tid = threadIdx.x;
    const int wid = tid >> 5;
    const int lid = tid & 31;
    const int n_blk = blockIdx.x;   // 0..7
    const int m_blk = blockIdx.y;   // 0..255

    const int wm = wid & 3, wn = wid >> 2;
    const int m0 = wm * 32, n0 = wn * 32;

    // ldmatrix lane addressing
    const int a_r  = (lid & 7) + ((lid >> 3) & 1) * 8;
    const int a_cs = (lid >> 4) * 16;
    const int b_r  = (lid & 7) + (lid >> 4) * 8;
    const int b_ks = ((lid >> 3) & 1) * 16;

    const __half* A = g_st_h + (size_t)m_blk * 128 * DIM;
    const __half* B = g_wkT_h + (size_t)n_blk * 128 * DIM;

    float acc[2][4][4];
    #pragma unroll
    for (int i = 0; i < 2; i++)
        #pragma unroll
        for (int j = 0; j < 4; j++)
            #pragma unroll
            for (int c = 0; c < 4; c++) acc[i][j][c] = 0.f;

    issue_slab(sbase, A, B, 0, tid);
    CP_COMMIT();

    for (int s = 0; s < 16; s++) {
        CP_WAIT0();
        __syncthreads();
        if (s < 15) {
            issue_slab(sbase + (uint32_t)((s + 1) & 1) * BUF_SZ, A, B,
                       (s + 1) * 64, tid);
            CP_COMMIT();
        }
        const uint32_t ab = sbase + (uint32_t)(s & 1) * BUF_SZ;

        #pragma unroll
        for (int kk = 0; kk < 4; kk++) {
            const int kb = kk * 32;    // 16 fp16 per k-step
            uint32_t ah[2][4], bf[4][2];
            #pragma unroll
            for (int fm = 0; fm < 2; fm++)
                LDMX4(ah[fm][0], ah[fm][1], ah[fm][2], ah[fm][3],
                      ab + OFF_A + (uint32_t)((m0 + fm * 16 + a_r) * PITCH + kb + a_cs));
            #pragma unroll
            for (int q = 0; q < 2; q++)
                LDMX4(bf[2 * q][0], bf[2 * q][1], bf[2 * q + 1][0], bf[2 * q + 1][1],
                      ab + OFF_B + (uint32_t)((n0 + q * 16 + b_r) * PITCH + kb + b_ks));
            #pragma unroll
            for (int fm = 0; fm < 2; fm++)
                #pragma unroll
                for (int fn = 0; fn < 4; fn++)
                    MMAF16(acc[fm][fn], ah[fm], bf[fn][0], bf[fn][1]);
        }
    }

    // Fused epilogue: tanh(relu(k + bk)) * We reduced over this 128-N tile
    float bkv[4][2], wev[4][2];
    #pragma unroll
    for (int fn = 0; fn < 4; fn++)
        #pragma unroll
        for (int j = 0; j < 2; j++) {
            const int n = n_blk * 128 + n0 + fn * 8 + (lid & 3) * 2 + j;
            bkv[fn][j] = bk[n];
            wev[fn][j] = We_k[n];
        }

    float* sred = (float*)(smem + RED_OFF);
    #pragma unroll
    for (int fm = 0; fm < 2; fm++)
        #pragma unroll
        for (int ch = 0; ch < 2; ch++) {
            float p = 0.f;
            #pragma unroll
            for (int fn = 0; fn < 4; fn++)
                #pragma unroll
                for (int j = 0; j < 2; j++) {
                    float v = acc[fm][fn][ch * 2 + j] + bkv[fn][j];
                    v = fmaxf(v, 0.f);
                    p = fmaf(tanhf(v), wev[fn][j], p);
                }
            p += __shfl_down_sync(0xffffffffu, p, 1, 4);
            p += __shfl_down_sync(0xffffffffu, p, 2, 4);
            if ((lid & 3) == 0)
                sred[wn * 128 + m0 + fm * 16 + ch * 8 + (lid >> 2)] = p;
        }
    __syncthreads();
    if (tid < 128) {
        const float e = sred[tid] + sred[128 + tid] + sred[256 + tid] + sred[384 + tid];
        g_ek_part[n_blk * M_TOT + m_blk * 128 + tid] = e;
    }
}

// ---------------------------------------------------------------------------
// softmax over s
// ---------------------------------------------------------------------------
__global__ void __launch_bounds__(256) k_softmax(
        const float* __restrict__ be, float* __restrict__ out_w) {
    const int b = blockIdx.x;
    const int tid = threadIdx.x;
    const float base = g_eq_part[b * 4 + 0] + g_eq_part[b * 4 + 1] +
                       g_eq_part[b * 4 + 2] + g_eq_part[b * 4 + 3] + be[0];
    float e[8];
    float lmax = -1e30f;
    #pragma unroll
    for (int r = 0; r < 8; r++) {
        const int s = r * 256 + tid;
        float v = base;
        #pragma unroll
        for (int p = 0; p < NSPLIT; p++)
            v += g_ek_part[p * M_TOT + b * SLEN + s];
        e[r] = v;
        lmax = fmaxf(lmax, v);
    }
    __shared__ float red[256];
    red[tid] = lmax; __syncthreads();
    for (int s = 128; s > 0; s >>= 1) {
        if (tid < s) red[tid] = fmaxf(red[tid], red[tid + s]);
        __syncthreads();
    }
    const float gmax = red[0];
    __syncthreads();
    float lsum = 0.f;
    #pragma unroll
    for (int r = 0; r < 8; r++) {
        e[r] = expf(e[r] - gmax);
        lsum += e[r];
    }
    red[tid] = lsum; __syncthreads();
    for (int s = 128; s > 0; s >>= 1) {
        if (tid < s) red[tid] += red[tid + s];
        __syncthreads();
    }
    const float inv = 1.f / red[0];
    #pragma unroll
    for (int r = 0; r < 8; r++)
        out_w[b * SLEN + r * 256 + tid] = e[r] * inv;
}

// ---------------------------------------------------------------------------
// attn partials + reduce
// ---------------------------------------------------------------------------
__global__ void __launch_bounds__(256) k_attn_part(
        const float* __restrict__ states, const float* __restrict__ w) {
    const int sc = blockIdx.x;   // 0..31
    const int b  = blockIdx.y;   // 0..15
    const int tid = threadIdx.x;
    const float4* st4 = (const float4*)states;
    float4 acc = make_float4(0.f, 0.f, 0.f, 0.f);
    const int s0 = sc * 64;
    #pragma unroll 4
    for (int sl = 0; sl < 64; sl++) {
        const int s = s0 + sl;
        const float wv = w[b * SLEN + s];
        const float4 v = st4[(size_t)(b * SLEN + s) * 256 + tid];
        acc.x = fmaf(wv, v.x, acc.x);
        acc.y = fmaf(wv, v.y, acc.y);
        acc.z = fmaf(wv, v.z, acc.z);
        acc.w = fmaf(wv, v.w, acc.w);
    }
    *(float4*)(g_attn_part + (size_t)(sc * BS + b) * DIM + tid * 4) = acc;
}

__global__ void __launch_bounds__(256) k_attn_reduce(float* __restrict__ out_attn) {
    const int idx = blockIdx.x * 256 + threadIdx.x;
    const int b = idx >> 10;
    const int d = idx & 1023;
    float s = 0.f;
    #pragma unroll
    for (int p = 0; p < 32; p++)
        s += g_attn_part[(size_t)(p * BS + b) * DIM + d];
    out_attn[idx] = s;
}

// ---------------------------------------------------------------------------
extern "C" void kernel_launch(void* const* d_in, const int* in_sizes, int n_in,
                              void* d_out, int out_size) {
    const float* query  = (const float*)d_in[0];
    const float* states = (const float*)d_in[1];
    const float* Wq     = (const float*)d_in[2];
    const float* bq     = (const float*)d_in[3];
    const float* Wk     = (const float*)d_in[4];
    const float* bk     = (const float*)d_in[5];
    const float* We     = (const float*)d_in[6];
    const float* be     = (const float*)d_in[7];

    float* out      = (float*)d_out;
    float* out_w    = out;                 // attn_weights (16, 2048)
    float* out_attn = out + BS * SLEN;     // attn         (16, 1024)

    cudaFuncSetAttribute(k_gemm_mma, cudaFuncAttributeMaxDynamicSharedMemorySize,
                         GEMM_SMEM);

    k_convert_states<<<M_TOT * DIM / 4 / 256, 256>>>(states);
    k_convert_wkT<<<dim3(32, 32), dim3(32, 8)>>>(Wk);
    k_qenergy<<<dim3(BS, 4), 256>>>(query, Wq, bq, We);
    k_gemm_mma<<<dim3(NSPLIT, M_TOT / 128), 512, GEMM_SMEM>>>(bk, We + DIM);
    k_softmax<<<BS, 256>>>(be, out_w);
    k_attn_part<<<dim3(32, BS), 256>>>(states, out_w);
    k_attn_reduce<<<BS * DIM / 256, 256>>>(out_attn);
}